// round 11
// baseline (speedup 1.0000x reference)
#include <cuda_runtime.h>
#include <cstdint>
#include <cstddef>
#include <type_traits>

constexpr int Bn = 8, Tn = 4096, Mn = 1024;
constexpr int THREADS = 256;          // each thread owns one float2 lane
constexpr int M2 = Mn / 2;            // 512 float2 per timestep
constexpr int CHUNKS = M2 / THREADS;  // 2
constexpr int STRIP = 64;             // timesteps per block
constexpr int NSTRIPS = Tn / STRIP;   // 64
constexpr int GSTEP = 4;              // timesteps per group
constexpr int NGRP = STRIP / GSTEP;   // 16 groups per strip
constexpr float EPSF = 1e-6f;

// Bump taps K[d] = exp(1 - 1/(1 - (d/15)^2 + 1e-6)), d=0..14 (K[15] == 0.0f in f32).
// Literals -> FFMA-imm form (rt_SMSP=1, zero tap registers).
__device__ constexpr float TAP[15] = {
    1.00000100f, 0.99554666f, 0.98206428f, 0.95919015f, 0.92630340f,
    0.88249802f, 0.82656660f, 0.75698827f, 0.67198882f, 0.56978420f,
    0.44933042f, 0.31240435f, 0.16901461f, 0.04890669f, 0.00116090f};

__device__ constexpr float PSUM[16] = {
    1.00000100f, 1.99554766f, 2.97761194f, 3.93680209f, 4.86310549f,
    5.74560351f, 6.57217011f, 7.32915838f, 8.00114720f, 8.57093140f,
    9.02026182f, 9.33266617f, 9.50168078f, 9.55058747f, 9.55174837f,
    9.55174837f};

// 3 CTAs/SM (24 warps, 50% occ) AND distance-2 prefetch: small 4-step groups
// keep data registers at 56 so the whole kernel fits the 84-reg budget.
__global__ void __launch_bounds__(THREADS, 3)
bump_conv_kernel(const float2* __restrict__ x,
                 const float*  __restrict__ gate_raw,
                 float2*       __restrict__ out) {
    const int mp = blockIdx.x * THREADS + threadIdx.x;  // float2 lane in [0, 512)
    const int b  = blockIdx.z;
    const int t0 = blockIdx.y * STRIP;

    const float g0 = log1pf(__expf(gate_raw[2 * mp]));
    const float g1 = log1pf(__expf(gate_raw[2 * mp + 1]));
    const float rS = 1.0f / fmaxf(PSUM[15], EPSF);
    const float c0 = g0 * rS, c1 = g1 * rS;

    const size_t base = ((size_t)b * Tn + t0) * M2 + mp;
    const float2* xp = x + base;
    float2*       op = out + base;

    // 7 rotating 4-step buffers; group g lives in buffer (g+4) % 7 (g >= -4).
    // Live set at comp(g): window g-4..g plus prefetched g+1, g+2  (= 7 groups).
    float2 Bf[7][GSTEP];

    auto load4 = [&](int bi, int tb) {
#pragma unroll
        for (int j = 0; j < GSTEP; ++j) Bf[bi][j] = xp[(tb + j) * M2];
    };

    // out[tb+j] = sum_{d=0..14} TAP[d] * x[tb+j-d].
    // cur = group tb/4, p1..p4 the four previous groups; all indices static.
    auto comp4 = [&](auto per_row, int cur, int p1, int p2, int p3, int p4,
                     int tb) {
#pragma unroll
        for (int j = 0; j < GSTEP; ++j) {
            float ax = TAP[0] * Bf[cur][j].x;
            float ay = TAP[0] * Bf[cur][j].y;
#pragma unroll
            for (int d = 1; d < 15; ++d) {
                int bi, sj = j - d;
                if (sj >= 0)        { bi = cur; }
                else if (sj >= -4)  { bi = p1; sj += 4;  }
                else if (sj >= -8)  { bi = p2; sj += 8;  }
                else if (sj >= -12) { bi = p3; sj += 12; }
                else                { bi = p4; sj += 16; }
                ax = fmaf(TAP[d], Bf[bi][sj].x, ax);
                ay = fmaf(TAP[d], Bf[bi][sj].y, ay);
            }
            float s0, s1;
            if constexpr (decltype(per_row)::value) {
                float rj = 1.0f / fmaxf(PSUM[tb + j], EPSF);  // rows t = 0..15
                s0 = g0 * rj; s1 = g1 * rj;
            } else {
                s0 = c0; s1 = c1;
            }
            op[(tb + j) * M2] = make_float2(ax * s0, ay * s1);
        }
    };

    // ---- prologue: history groups -4..-1 (buffers 0..3), prefetch g=0,1,2 ----
    if (t0 == 0) {
#pragma unroll
        for (int bi = 0; bi < 4; ++bi)
#pragma unroll
            for (int j = 0; j < GSTEP; ++j) Bf[bi][j] = make_float2(0.f, 0.f);
    } else {
        load4(0, -16);   // g=-4 (only idx 2,3 used)
        load4(1, -12);   // g=-3
        load4(2, -8);    // g=-2
        load4(3, -4);    // g=-1
    }
    load4(4, 0);   // g=0
    load4(5, 4);   // g=1
    load4(6, 8);   // g=2

    // ---- steady pipeline: comp(g); then load(g+3) into freed buffer g%7 ----
    if (t0 == 0) {
#pragma unroll
        for (int g = 0; g < NGRP; ++g) {
            if (g < 4)
                comp4(std::true_type{}, (g + 4) % 7, (g + 3) % 7, (g + 2) % 7,
                      (g + 1) % 7, g % 7, GSTEP * g);
            else
                comp4(std::false_type{}, (g + 4) % 7, (g + 3) % 7, (g + 2) % 7,
                      (g + 1) % 7, g % 7, GSTEP * g);
            if (g + 3 < NGRP) load4(g % 7, GSTEP * (g + 3));
        }
    } else {
#pragma unroll
        for (int g = 0; g < NGRP; ++g) {
            comp4(std::false_type{}, (g + 4) % 7, (g + 3) % 7, (g + 2) % 7,
                  (g + 1) % 7, g % 7, GSTEP * g);
            if (g + 3 < NGRP) load4(g % 7, GSTEP * (g + 3));
        }
    }
}

extern "C" void kernel_launch(void* const* d_in, const int* in_sizes, int n_in,
                              void* d_out, int out_size) {
    const float* x        = (const float*)d_in[0];
    // d_in[1] (mask) is exactly tril(ones); already encoded in the causal taps.
    const float* gate_raw = (const float*)d_in[2];

    dim3 grid(CHUNKS, NSTRIPS, Bn);
    bump_conv_kernel<<<grid, THREADS>>>((const float2*)x, gate_raw, (float2*)d_out);
}

// round 12
// speedup vs baseline: 1.4890x; 1.4890x over previous
#include <cuda_runtime.h>
#include <cstdint>
#include <cstddef>
#include <type_traits>

constexpr int Bn = 8, Tn = 4096, Mn = 1024;
constexpr int THREADS = 256;            // each thread owns one float2 lane
constexpr int M2 = Mn / 2;              // 512 float2 per timestep
constexpr int CHUNKS = M2 / THREADS;    // 2
constexpr int STRIP = 64;               // timesteps per block (8 groups of 8)
constexpr int NSTRIPS = Tn / STRIP;     // 64
constexpr int NSLOT = 6;                // smem ring slots (1 group = 8 steps each)
constexpr int SMEM_BYTES = NSLOT * 8 * THREADS * 8;  // 96 KB
constexpr float EPSF = 1e-6f;

// Bump taps K[d] = exp(1 - 1/(1 - (d/15)^2 + 1e-6)), d=0..14 (K[15] == 0.0f in f32).
// Literals -> FFMA-imm form (rt_SMSP=1, zero tap registers).
__device__ constexpr float TAP[15] = {
    1.00000100f, 0.99554666f, 0.98206428f, 0.95919015f, 0.92630340f,
    0.88249802f, 0.82656660f, 0.75698827f, 0.67198882f, 0.56978420f,
    0.44933042f, 0.31240435f, 0.16901461f, 0.04890669f, 0.00116090f};

__device__ constexpr float PSUM[16] = {
    1.00000100f, 1.99554766f, 2.97761194f, 3.93680209f, 4.86310549f,
    5.74560351f, 6.57217011f, 7.32915838f, 8.00114720f, 8.57093140f,
    9.02026182f, 9.33266617f, 9.50168078f, 9.55058747f, 9.55174837f,
    9.55174837f};

__device__ __forceinline__ void cp8(uint32_t dst, const float2* src) {
    asm volatile("cp.async.ca.shared.global [%0], [%1], 8;"
                 :: "r"(dst), "l"(src) : "memory");
}
__device__ __forceinline__ void cp_commit() {
    asm volatile("cp.async.commit_group;" ::: "memory");
}
template <int N> __device__ __forceinline__ void cp_wait() {
    asm volatile("cp.async.wait_group %0;" :: "n"(N) : "memory");
}

extern __shared__ float2 sring[];  // [NSLOT][8][THREADS]

__global__ void __launch_bounds__(THREADS, 2)
bump_conv_kernel(const float2* __restrict__ x,
                 const float*  __restrict__ gate_raw,
                 float2*       __restrict__ out) {
    const int tid = threadIdx.x;
    const int mp  = blockIdx.x * THREADS + tid;   // float2 lane in [0, 512)
    const int b   = blockIdx.z;
    const int t0  = blockIdx.y * STRIP;

    const float g0 = log1pf(__expf(gate_raw[2 * mp]));
    const float g1 = log1pf(__expf(gate_raw[2 * mp + 1]));
    const float rS = 1.0f / fmaxf(PSUM[15], EPSF);
    const float c0 = g0 * rS, c1 = g1 * rS;

    const size_t base = ((size_t)b * Tn + t0) * M2 + mp;
    const float2* xp = x + base;
    float2*       op = out + base;

    uint32_t smem0;
    asm("{ .reg .u64 t0; cvta.to.shared.u64 t0, %1; cvt.u32.u64 %0, t0; }"
        : "=r"(smem0) : "l"(sring));
    const uint32_t laneByte = smem0 + tid * 8;

    // Issue one group's 8 lane-loads (fire-and-forget) into smem slot, commit.
    auto issue8 = [&](int slot, int g) {
#pragma unroll
        for (int j = 0; j < 8; ++j)
            cp8(laneByte + (uint32_t)((slot * 8 + j) * (THREADS * 8)),
                xp + (8 * g + j) * M2);
        cp_commit();
    };
    // Pull one group from its smem slot into a register buffer (own lane only;
    // no cross-thread data -> no barrier needed).
    auto pull8 = [&](float2 (&buf)[8], int slot) {
#pragma unroll
        for (int j = 0; j < 8; ++j)
            buf[j] = sring[(slot * 8 + j) * THREADS + tid];
    };

    // out[tb+j] = sum_{d=0..14} TAP[d] * x[tb+j-d]; cur=tb, p1=tb-8, p2=tb-16.
    auto comp8 = [&](auto per_row, const float2 (&cur)[8], const float2 (&p1)[8],
                     const float2 (&p2)[8], int tb) {
#pragma unroll
        for (int j = 0; j < 8; ++j) {
            float ax = TAP[0] * cur[j].x;
            float ay = TAP[0] * cur[j].y;
#pragma unroll
            for (int d = 1; d < 15; ++d) {  // all indices compile-time
                if (d <= j) {
                    ax = fmaf(TAP[d], cur[j - d].x, ax);
                    ay = fmaf(TAP[d], cur[j - d].y, ay);
                } else if (d <= j + 8) {
                    ax = fmaf(TAP[d], p1[j - d + 8].x, ax);
                    ay = fmaf(TAP[d], p1[j - d + 8].y, ay);
                } else {
                    ax = fmaf(TAP[d], p2[j - d + 16].x, ax);
                    ay = fmaf(TAP[d], p2[j - d + 16].y, ay);
                }
            }
            float s0, s1;
            if constexpr (decltype(per_row)::value) {
                float rj = 1.0f / fmaxf(PSUM[tb + j], EPSF);  // rows t = 0..15
                s0 = g0 * rj; s1 = g1 * rj;
            } else {
                s0 = c0; s1 = c1;
            }
            op[(tb + j) * M2] = make_float2(ax * s0, ay * s1);
        }
    };

    // Register window: A, B, C rotate through (cur, p1, p2).
    float2 A[8], B[8], C[8];
    constexpr std::false_type F{};

    // slot(g) = (g+2) mod 6 for groups g = -2..7.
    if (t0 == 0) {
        // No halo; history regs are zeros. Commits: groups 0,1,2,3.
        issue8(2, 0); issue8(3, 1); issue8(4, 2); issue8(5, 3);
#pragma unroll
        for (int k = 0; k < 8; ++k) { A[k] = make_float2(0.f, 0.f);   // g=-2
                                      B[k] = make_float2(0.f, 0.f); } // g=-1
        cp_wait<3>(); pull8(C, 2);                     // g0 ready
        comp8(std::true_type{}, C, B, A, 0);           // t=0..7 per-row norm
        issue8(0, 4);
        cp_wait<3>(); pull8(A, 3);
        comp8(std::true_type{}, A, C, B, 8);           // t=8..15 per-row norm
        issue8(1, 5);
    } else {
        // Halo groups -2, -1 then 0..3. Commits: [-2,-1,0,1,2,3].
        issue8(0, -2); issue8(1, -1);
        issue8(2, 0);  issue8(3, 1); issue8(4, 2); issue8(5, 3);
        cp_wait<4>();                                  // halo groups complete
        pull8(A, 0);                                   // g=-2
        pull8(B, 1);                                   // g=-1
        cp_wait<3>(); pull8(C, 2);                     // g0
        comp8(F, C, B, A, 0);
        issue8(0, 4);
        cp_wait<3>(); pull8(A, 3);                     // g1
        comp8(F, A, C, B, 8);
        issue8(1, 5);
    }

    // Steady state: groups 2..7. Before group g, allow min(3, 7-g) pending.
    cp_wait<3>(); pull8(B, 4);  comp8(F, B, A, C, 16);  issue8(2, 6);  // g2
    cp_wait<3>(); pull8(C, 5);  comp8(F, C, B, A, 24);  issue8(3, 7);  // g3
    cp_wait<3>(); pull8(A, 0);  comp8(F, A, C, B, 32);                 // g4
    cp_wait<2>(); pull8(B, 1);  comp8(F, B, A, C, 40);                 // g5
    cp_wait<1>(); pull8(C, 2);  comp8(F, C, B, A, 48);                 // g6
    cp_wait<0>(); pull8(A, 3);  comp8(F, A, C, B, 56);                 // g7
}

extern "C" void kernel_launch(void* const* d_in, const int* in_sizes, int n_in,
                              void* d_out, int out_size) {
    const float* x        = (const float*)d_in[0];
    // d_in[1] (mask) is exactly tril(ones); already encoded in the causal taps.
    const float* gate_raw = (const float*)d_in[2];

    cudaFuncSetAttribute(bump_conv_kernel,
                         cudaFuncAttributeMaxDynamicSharedMemorySize, SMEM_BYTES);
    dim3 grid(CHUNKS, NSTRIPS, Bn);
    bump_conv_kernel<<<grid, THREADS, SMEM_BYTES>>>((const float2*)x, gate_raw,
                                                    (float2*)d_out);
}

// round 13
// speedup vs baseline: 1.6803x; 1.1284x over previous
#include <cuda_runtime.h>
#include <cstdint>
#include <cstddef>
#include <type_traits>

constexpr int Bn = 8, Tn = 4096, Mn = 1024;
constexpr int THREADS = 256;          // each thread owns one float2 lane
constexpr int M2 = Mn / 2;            // 512 float2 per timestep
constexpr int CHUNKS = M2 / THREADS;  // 2
constexpr int STRIP = 64;             // timesteps per block
constexpr int NSTRIPS = Tn / STRIP;   // 64
constexpr float EPSF = 1e-6f;

// Bump taps K[d] = exp(1 - 1/(1 - (d/15)^2 + 1e-6)), d=0..14 (K[15] == 0.0f in f32).
// Literals -> FFMA-imm form (rt_SMSP=1, zero tap registers).
__device__ constexpr float TAP[15] = {
    1.00000100f, 0.99554666f, 0.98206428f, 0.95919015f, 0.92630340f,
    0.88249802f, 0.82656660f, 0.75698827f, 0.67198882f, 0.56978420f,
    0.44933042f, 0.31240435f, 0.16901461f, 0.04890669f, 0.00116090f};

__device__ constexpr float PSUM[16] = {
    1.00000100f, 1.99554766f, 2.97761194f, 3.93680209f, 4.86310549f,
    5.74560351f, 6.57217011f, 7.32915838f, 8.00114720f, 8.57093140f,
    9.02026182f, 9.33266617f, 9.50168078f, 9.55058747f, 9.55174837f,
    9.55174837f};

__global__ void __launch_bounds__(THREADS, 2)
bump_conv_kernel(const float2* __restrict__ x,
                 const float*  __restrict__ gate_raw,
                 float2*       __restrict__ out) {
    const int mp = blockIdx.x * THREADS + threadIdx.x;  // float2 lane in [0, 512)
    const int b  = blockIdx.z;
    const int t0 = blockIdx.y * STRIP;

    const float g0 = log1pf(__expf(gate_raw[2 * mp]));
    const float g1 = log1pf(__expf(gate_raw[2 * mp + 1]));
    const float rS = 1.0f / fmaxf(PSUM[15], EPSF);
    const float c0 = g0 * rS, c1 = g1 * rS;

    const size_t base = ((size_t)b * Tn + t0) * M2 + mp;
    const float2* xp = x + base;
    float2*       op = out + base;

    // 5 rotating 8-timestep buffers: cur, prev1, prev2 (15-tap window)
    // + two prefetch slots (load(g+2) issued 2 comp-groups before use).
    float2 B0[8], B1[8], B2[8], B3[8], B4[8];

    auto load8 = [&](float2 (&buf)[8], int tb) {
#pragma unroll
        for (int j = 0; j < 8; ++j) buf[j] = xp[(tb + j) * M2];  // imm offsets
    };

    // out[tb+j] = sum_{d=0..14} TAP[d] * x[tb+j-d]
    // cur = group tb, p1 = tb-8, p2 = tb-16 (only idx >= 2 of p2 read).
    // Output uses streaming stores (.cs): out is write-once, keep x in L2.
    auto comp8 = [&](auto per_row, const float2 (&cur)[8], const float2 (&p1)[8],
                     const float2 (&p2)[8], int tb) {
#pragma unroll
        for (int j = 0; j < 8; ++j) {
            float ax = TAP[0] * cur[j].x;
            float ay = TAP[0] * cur[j].y;
#pragma unroll
            for (int d = 1; d < 15; ++d) {  // j, d compile-time -> static selection
                if (d <= j) {
                    ax = fmaf(TAP[d], cur[j - d].x, ax);
                    ay = fmaf(TAP[d], cur[j - d].y, ay);
                } else if (d <= j + 8) {
                    ax = fmaf(TAP[d], p1[j - d + 8].x, ax);
                    ay = fmaf(TAP[d], p1[j - d + 8].y, ay);
                } else {
                    ax = fmaf(TAP[d], p2[j - d + 16].x, ax);
                    ay = fmaf(TAP[d], p2[j - d + 16].y, ay);
                }
            }
            float s0, s1;
            if constexpr (decltype(per_row)::value) {
                float rj = 1.0f / fmaxf(PSUM[tb + j], EPSF);  // rows t = 0..15
                s0 = g0 * rj; s1 = g1 * rj;
            } else {
                s0 = c0; s1 = c1;
            }
            __stcs(&op[(tb + j) * M2], make_float2(ax * s0, ay * s1));
        }
    };

    constexpr std::false_type F{};

    // ---- prologue: 5 load batches in flight before the first compute ----
    // groups: -2 -> B3, -1 -> B4, 0 -> B0, 1 -> B1, 2 -> B2
    if (t0 == 0) {
#pragma unroll
        for (int k = 0; k < 8; ++k) { B3[k] = make_float2(0.f, 0.f);
                                      B4[k] = make_float2(0.f, 0.f); }
        load8(B0, 0);
        load8(B1, 8);
        load8(B2, 16);
        comp8(std::true_type{}, B0, B4, B3, 0);   // t = 0..7  per-row normalizer
        load8(B3, 24);                            // g=3
        comp8(std::true_type{}, B1, B0, B4, 8);   // t = 8..15 per-row normalizer
    } else {
        load8(B3, -16);   // halo g=-2 (idx 0,1 unused; in-bounds since t0 >= 64)
        load8(B4, -8);    // halo g=-1
        load8(B0, 0);
        load8(B1, 8);
        load8(B2, 16);
        comp8(F, B0, B4, B3, 0);                  // g=0
        load8(B3, 24);                            // g=3
        comp8(F, B1, B0, B4, 8);                  // g=1
    }

    // ---- steady pipeline, distance-2 prefetch ----
    load8(B4, 32);             // g=4
    comp8(F, B2, B1, B0, 16);  // g=2
    load8(B0, 40);             // g=5
    comp8(F, B3, B2, B1, 24);  // g=3
    load8(B1, 48);             // g=6
    comp8(F, B4, B3, B2, 32);  // g=4
    load8(B2, 56);             // g=7
    comp8(F, B0, B4, B3, 40);  // g=5
    comp8(F, B1, B0, B4, 48);  // g=6
    comp8(F, B2, B1, B0, 56);  // g=7
}

extern "C" void kernel_launch(void* const* d_in, const int* in_sizes, int n_in,
                              void* d_out, int out_size) {
    const float* x        = (const float*)d_in[0];
    // d_in[1] (mask) is exactly tril(ones); already encoded in the causal taps.
    const float* gate_raw = (const float*)d_in[2];

    dim3 grid(CHUNKS, NSTRIPS, Bn);
    bump_conv_kernel<<<grid, THREADS>>>((const float2*)x, gate_raw, (float2*)d_out);
}